// round 11
// baseline (speedup 1.0000x reference)
#include <cuda_runtime.h>
#include <cuda_bf16.h>
#include <cuda_fp16.h>
#include <math.h>
#include <cstdint>

constexpr int Bb = 8, Ll = 2048, Hh = 256;
constexpr int JT = 64, NC = Ll / JT;   // pass2 j-chunks
constexpr int STRB = 144;              // padded smem row stride (bytes), 9x16B

// ---------------- device scratch (allocation-free) ---------------------------
__device__ float  g_st[Bb * Ll];
__device__ float  g_so[Bb * Ll];
__device__ float  g_q [Bb * Ll];                     // mult_j * log2(e)
__device__ float2 g_qs[Bb * Ll];                     // {q_j, q_j * so_j}
__device__ float  g_c [Bb * Ll];                     // -(m̂_i + log2 l_i)
__device__ float  g_base[Ll];
__device__ __half g_vh[(size_t)Bb * Hh * Ll];        // V^T [B][H][L] fp16
__device__ __nv_bfloat16 g_whi[2 * Hh * Hh];         // W hi  [sel][h][k]
__device__ __nv_bfloat16 g_wlo[2 * Hh * Hh];         // W lo residual
__device__ __nv_bfloat16 g_xthi[Bb * Ll * Hh];       // text  hi [m][k]
__device__ __nv_bfloat16 g_xtlo[Bb * Ll * Hh];       // text  lo
__device__ __nv_bfloat16 g_xohi[Bb * Ll * Hh];       // opinion hi [m][k]
__device__ __nv_bfloat16 g_xolo[Bb * Ll * Hh];       // opinion lo

// ---------------- small helpers ----------------------------------------------
__device__ __forceinline__ uint32_t su32(const void* p) {
    return (uint32_t)__cvta_generic_to_shared(p);
}
__device__ __forceinline__ float ex2f(float x) {
    float r; asm("ex2.approx.f32 %0, %1;" : "=f"(r) : "f"(x)); return r;
}
__device__ __forceinline__ float lg2f(float x) {
    float r; asm("lg2.approx.f32 %0, %1;" : "=f"(r) : "f"(x)); return r;
}
__device__ __forceinline__ void ldm4(uint32_t& r0, uint32_t& r1, uint32_t& r2,
                                     uint32_t& r3, uint32_t a) {
    asm volatile("ldmatrix.sync.aligned.m8n8.x4.shared.b16 {%0,%1,%2,%3}, [%4];"
        : "=r"(r0), "=r"(r1), "=r"(r2), "=r"(r3) : "r"(a));
}
__device__ __forceinline__ void mma16816bf(float* c, const uint32_t* a,
                                           uint32_t b0, uint32_t b1) {
    asm volatile("mma.sync.aligned.m16n8k16.row.col.f32.bf16.bf16.f32 "
        "{%0,%1,%2,%3}, {%4,%5,%6,%7}, {%8,%9}, {%0,%1,%2,%3};"
        : "+f"(c[0]), "+f"(c[1]), "+f"(c[2]), "+f"(c[3])
        : "r"(a[0]), "r"(a[1]), "r"(a[2]), "r"(a[3]), "r"(b0), "r"(b1));
}
__device__ __forceinline__ void mma16816h(float* c, const uint32_t* a,
                                          uint32_t b0, uint32_t b1) {
    asm volatile("mma.sync.aligned.m16n8k16.row.col.f32.f16.f16.f32 "
        "{%0,%1,%2,%3}, {%4,%5,%6,%7}, {%8,%9}, {%0,%1,%2,%3};"
        : "+f"(c[0]), "+f"(c[1]), "+f"(c[2]), "+f"(c[3])
        : "r"(a[0]), "r"(a[1]), "r"(a[2]), "r"(a[3]), "r"(b0), "r"(b1));
}
__device__ __forceinline__ void split2(float p0, float p1, uint32_t& hi, uint32_t& lo) {
    asm("cvt.rn.bf16x2.f32 %0, %1, %2;" : "=r"(hi) : "f"(p1), "f"(p0));
    float h0 = __uint_as_float(hi << 16);
    float h1 = __uint_as_float(hi & 0xffff0000u);
    float r0 = p0 - h0, r1 = p1 - h1;
    asm("cvt.rn.bf16x2.f32 %0, %1, %2;" : "=r"(lo) : "f"(r1), "f"(r0));
}
__device__ __forceinline__ uint32_t packh2(float p0, float p1) {
    uint32_t r;
    asm("cvt.rn.f16x2.f32 %0, %1, %2;" : "=r"(r) : "f"(p1), "f"(p0));
    return r;
}
__device__ __forceinline__ void cp16(uint32_t dst, const void* src) {
    asm volatile("cp.async.cg.shared.global [%0], [%1], 16;"
        :: "r"(dst), "l"(src) : "memory");
}
#define CP_COMMIT() asm volatile("cp.async.commit_group;" ::: "memory")
#define CP_WAIT0()  asm volatile("cp.async.wait_group 0;" ::: "memory")

// ---------------- mega-prep: all preprocessing in one launch -----------------
// zones by blockIdx.x: [0,64) prep0 | [64,576) prepw | [576,16960) prept |
// [16960,21056) prepv(+opinion split)
__global__ __launch_bounds__(256) void prep_kernel(
    const int* __restrict__ pos, const float* __restrict__ Wt,
    const float* __restrict__ Wo, const float* __restrict__ Xt,
    const float* __restrict__ V)
{
    __shared__ float tile[32][33];
    const int blk = blockIdx.x, tid = threadIdx.x;
    if (blk < 64) {
        int idx = blk * 256 + tid;
        int p = pos[idx];
        bool op = (p >= 19 && p <= 21) || (p >= 33 && p <= 35) || (p >= 41 && p <= 46);
        g_q[idx] = (op ? 8.0f : 1.0f) * 1.44269504088896340736f;
        if (idx < Ll)
            g_base[idx] = (idx == 0) ? 0.5f : (1.0f / log2f(2.0f + (float)idx));
    } else if (blk < 576) {
        int idx = (blk - 64) * 256 + tid;
        int sel = idx >> 16, i = idx & (Hh * Hh - 1);
        float w = sel ? Wo[i] : Wt[i];
        __nv_bfloat16 hi = __float2bfloat16(w);
        g_whi[idx] = hi;
        g_wlo[idx] = __float2bfloat16(w - __bfloat162float(hi));
    } else if (blk < 16960) {
        int idx = (blk - 576) * 256 + tid;
        float v = Xt[idx];
        __nv_bfloat16 hi = __float2bfloat16(v);
        g_xthi[idx] = hi;
        g_xtlo[idx] = __float2bfloat16(v - __bfloat162float(hi));
    } else {
        int vz = blk - 16960;
        const int j0 = (vz & 63) * 32, h0 = ((vz >> 6) & 7) * 32, b = vz >> 9;
        const int c = tid & 31, r0 = tid >> 5;
        #pragma unroll
        for (int k = 0; k < 4; ++k) {
            int r = r0 + k * 8;
            size_t lin = ((size_t)b * Ll + j0 + r) * Hh + h0 + c;
            float v = V[lin];
            tile[r][c] = v;
            __nv_bfloat16 hi = __float2bfloat16(v);
            g_xohi[lin] = hi;
            g_xolo[lin] = __float2bfloat16(v - __bfloat162float(hi));
        }
        __syncthreads();
        #pragma unroll
        for (int k = 0; k < 4; ++k) {
            int hh = r0 + k * 8;
            g_vh[((size_t)b * Hh + h0 + hh) * Ll + j0 + c] = __float2half(tile[c][hh]);
        }
    }
}

// ---------------- stage 1: 512-thread bf16-split MMA + tanh·wa ---------------
// 16 warps: 2 m-groups (64 rows) x 8 h-groups (32 cols); warp tile 64m x 32h.
constexpr int S1_XHI = 0;                          // [2][128][STRB]
constexpr int S1_XLO = 2 * 128 * STRB;             // 36864
constexpr int S1_WHI = 4 * 128 * STRB;             // 73728  [2][256][STRB]
constexpr int S1_WLO = S1_WHI + 2 * 256 * STRB;    // 147456
constexpr int S1_RED = S1_WLO + 2 * 256 * STRB;    // 221184: float[8][128]
constexpr int S1_SMEM = S1_RED + 8 * 128 * 4;      // 225280

__global__ __launch_bounds__(512, 1) void s1_mma_kernel(
    const float* __restrict__ bt, const float* __restrict__ wa)
{
    extern __shared__ char smc[];
    const int tid = threadIdx.x, wid = tid >> 5, lane = tid & 31;
    const int sel = blockIdx.x >> 7;
    const int m0 = (blockIdx.x & 127) * 128;
    const int wi = wid >> 3;     // 0..1: 64 m-rows
    const int wh = wid & 7;      // 0..7: 32 h-cols

    const float* bias = sel ? nullptr : bt;
    const float* wah = wa + sel * Hh;
    const __nv_bfloat16* xhiG = (sel ? g_xohi : g_xthi) + (size_t)m0 * Hh;
    const __nv_bfloat16* xloG = (sel ? g_xolo : g_xtlo) + (size_t)m0 * Hh;
    const __nv_bfloat16* whiG = g_whi + sel * Hh * Hh;
    const __nv_bfloat16* wloG = g_wlo + sel * Hh * Hh;

    const int sub = lane >> 3, lr = lane & 7;
    const uint32_t lrA = (uint32_t)((lr + (sub & 1) * 8) * STRB + (sub >> 1) * 16);
    const uint32_t lrB = (uint32_t)((lr + (sub >> 1) * 8) * STRB + (sub & 1) * 16);

    float C[4][4][4] = {};

    auto fill = [&](int bf, int kc) {
        #pragma unroll
        for (int k = 0; k < 2; ++k) {
            int idx = tid + k * 512;
            int r = idx >> 3, seg = idx & 7;
            cp16(su32(smc + S1_XHI + bf * 128 * STRB + r * STRB + seg * 16),
                 xhiG + (size_t)r * Hh + kc * 64 + seg * 8);
            cp16(su32(smc + S1_XLO + bf * 128 * STRB + r * STRB + seg * 16),
                 xloG + (size_t)r * Hh + kc * 64 + seg * 8);
        }
        #pragma unroll
        for (int k = 0; k < 4; ++k) {
            int idx = tid + k * 512;
            int r = idx >> 3, seg = idx & 7;
            cp16(su32(smc + S1_WHI + bf * 256 * STRB + r * STRB + seg * 16),
                 whiG + (size_t)r * Hh + kc * 64 + seg * 8);
            cp16(su32(smc + S1_WLO + bf * 256 * STRB + r * STRB + seg * 16),
                 wloG + (size_t)r * Hh + kc * 64 + seg * 8);
        }
        CP_COMMIT();
    };

    fill(0, 0);
    CP_WAIT0();
    __syncthreads();

    for (int kc = 0; kc < 4; ++kc) {
        const int s = kc & 1;
        if (kc + 1 < 4) fill(s ^ 1, kc + 1);
        const uint32_t xhi = su32(smc + S1_XHI + s * 128 * STRB);
        const uint32_t xlo = su32(smc + S1_XLO + s * 128 * STRB);
        const uint32_t whi = su32(smc + S1_WHI + s * 256 * STRB);
        const uint32_t wlo = su32(smc + S1_WLO + s * 256 * STRB);
        #pragma unroll
        for (int kk = 0; kk < 4; ++kk) {
            const uint32_t kb = kk * 32;
            uint32_t bh[2][4], bl[2][4];
            #pragma unroll
            for (int nt2 = 0; nt2 < 2; ++nt2) {
                uint32_t off = (uint32_t)((wh * 32 + nt2 * 16) * STRB) + kb + lrB;
                ldm4(bh[nt2][0], bh[nt2][1], bh[nt2][2], bh[nt2][3], whi + off);
                ldm4(bl[nt2][0], bl[nt2][1], bl[nt2][2], bl[nt2][3], wlo + off);
            }
            #pragma unroll
            for (int mt = 0; mt < 4; ++mt) {
                uint32_t aoff = (uint32_t)((wi * 64 + mt * 16) * STRB) + kb + lrA;
                uint32_t ah[4], al[4];
                ldm4(ah[0], ah[1], ah[2], ah[3], xhi + aoff);
                ldm4(al[0], al[1], al[2], al[3], xlo + aoff);
                #pragma unroll
                for (int nt2 = 0; nt2 < 2; ++nt2) {
                    mma16816bf(C[mt][2 * nt2],     ah, bh[nt2][0], bh[nt2][1]);
                    mma16816bf(C[mt][2 * nt2 + 1], ah, bh[nt2][2], bh[nt2][3]);
                }
                #pragma unroll
                for (int nt2 = 0; nt2 < 2; ++nt2) {
                    mma16816bf(C[mt][2 * nt2],     al, bh[nt2][0], bh[nt2][1]);
                    mma16816bf(C[mt][2 * nt2 + 1], al, bh[nt2][2], bh[nt2][3]);
                }
                #pragma unroll
                for (int nt2 = 0; nt2 < 2; ++nt2) {
                    mma16816bf(C[mt][2 * nt2],     ah, bl[nt2][0], bl[nt2][1]);
                    mma16816bf(C[mt][2 * nt2 + 1], ah, bl[nt2][2], bl[nt2][3]);
                }
            }
        }
        if (kc + 1 < 4) CP_WAIT0();
        __syncthreads();
    }

    // epilogue: s[m] = sum_h tanh(C + bias_h) * wa_h
    float* sred = (float*)(smc + S1_RED);
    const int g = lane >> 2, tig = lane & 3;
    #pragma unroll
    for (int mt = 0; mt < 4; ++mt) {
        float p0 = 0.f, p1 = 0.f;
        #pragma unroll
        for (int nt = 0; nt < 4; ++nt) {
            int h = wh * 32 + nt * 8 + tig * 2;
            float b0 = bias ? __ldg(bias + h)     : 0.f;
            float b1 = bias ? __ldg(bias + h + 1) : 0.f;
            float w0 = __ldg(wah + h), w1 = __ldg(wah + h + 1);
            p0 += tanhf(C[mt][nt][0] + b0) * w0 + tanhf(C[mt][nt][1] + b1) * w1;
            p1 += tanhf(C[mt][nt][2] + b0) * w0 + tanhf(C[mt][nt][3] + b1) * w1;
        }
        p0 += __shfl_xor_sync(0xffffffffu, p0, 1);
        p0 += __shfl_xor_sync(0xffffffffu, p0, 2);
        p1 += __shfl_xor_sync(0xffffffffu, p1, 1);
        p1 += __shfl_xor_sync(0xffffffffu, p1, 2);
        if (tig == 0) {
            int row = wi * 64 + mt * 16 + g;
            sred[wh * 128 + row]     = p0;
            sred[wh * 128 + row + 8] = p1;
        }
    }
    __syncthreads();
    if (tid < 128) {
        float acc = 0.f;
        #pragma unroll
        for (int k = 0; k < 8; ++k) acc += sred[k * 128 + tid];
        float* outS = sel ? g_so : g_st;
        outS[m0 + tid] = acc;
    }
}

// ---------------- pass 1: single-pass stats via safe max bound ---------------
__global__ __launch_bounds__(256) void pass1_kernel(const float* __restrict__ ba) {
    __shared__ float2 sQS[Ll];
    __shared__ float  sB[Ll];
    __shared__ float  sred[8];
    const int b = blockIdx.y, i0 = blockIdx.x * 128;
    const int tid = threadIdx.x, wid = tid >> 5, lane = tid & 31;

    float somax = -INFINITY;
    for (int t = tid; t < Ll; t += 256) {
        float so = g_so[b * Ll + t];
        float q  = g_q [b * Ll + t];
        float2 v = make_float2(q, q * so);
        sQS[t] = v;
        sB[t]  = g_base[t];
        if ((unsigned)(t - i0) < 128u) g_qs[b * Ll + t] = v;
        somax = fmaxf(somax, so);
    }
    #pragma unroll
    for (int off = 16; off > 0; off >>= 1)
        somax = fmaxf(somax, __shfl_xor_sync(0xffffffffu, somax, off));
    if (lane == 0) sred[wid] = somax;
    __syncthreads();
    somax = fmaxf(fmaxf(fmaxf(sred[0], sred[1]), fmaxf(sred[2], sred[3])),
                  fmaxf(fmaxf(sred[4], sred[5]), fmaxf(sred[6], sred[7])));

    const int row = tid >> 1, half = tid & 1;
    const int gi = i0 + row;
    const float A = g_st[b * Ll + gi] + ba[0];
    const float apm = A + somax;
    const float mhat = apm > 0.0f ? apm * 7.2825f : apm * 0.1311f;
    const int jb = half * 1024;

    float l = 0.f;
    #pragma unroll 4
    for (int t = 0; t < 1024; ++t) {
        int j = jb + t;
        int d = gi - j; d = d < 0 ? -d : d;
        float2 v = sQS[j];
        float x = fmaf(A, v.x, v.y) * sB[d];
        l += ex2f(x - mhat);
    }
    l += __shfl_xor_sync(0xffffffffu, l, 1);
    if (half == 0) g_c[b * Ll + gi] = -(mhat + lg2f(l));
}

// ---------------- pass 2: 512-thread register-P fp16 MMA attention -----------
// 16 warps: 4 i-groups (32 rows) x 4 h-groups (64 cols); warp tile 32i x 64h.
constexpr int P2_V    = 0;                        // [2][256*STRB] fp16 V^T
constexpr int P2_QS   = 2 * 256 * STRB;           // [2][512B]
constexpr int P2_BASE = P2_QS + 1024;             // float[2048]
constexpr int P2_SMEM = P2_BASE + Ll * 4;         // 82944

__global__ __launch_bounds__(512, 1) void pass2_kernel(
    const float* __restrict__ ba, float* __restrict__ out)
{
    extern __shared__ char smc[];
    const int tid = threadIdx.x, wid = tid >> 5, lane = tid & 31;
    const int b = blockIdx.y, i0 = blockIdx.x * 128;
    const int wi = wid >> 2;   // 0..3: 32 i-rows
    const int wh = wid & 3;    // 0..3: 64 h-cols
    const int r = lane >> 2, c = lane & 3;

    float* sBase = (float*)(smc + P2_BASE);

    const int sub = lane >> 3, lr = lane & 7;
    const uint32_t lrB = (uint32_t)((lr + (sub >> 1) * 8) * STRB + (sub & 1) * 16);

    const __half* v_g = g_vh + (size_t)b * Hh * Ll;
    const float2* qs_g = g_qs + b * Ll;

    float stiV[4], ciV[4];
    int giV[4];
    {
        const float ba0 = __ldg(ba);
        #pragma unroll
        for (int u = 0; u < 4; ++u) {
            int gi = i0 + wi * 32 + (u >> 1) * 16 + r + (u & 1) * 8;
            giV[u] = gi;
            stiV[u] = g_st[b * Ll + gi] + ba0;
            ciV[u]  = g_c [b * Ll + gi];
        }
    }

    auto loadV = [&](int bf, int j0) {
        #pragma unroll
        for (int k = 0; k < 4; ++k) {
            int idx = tid + k * 512;
            int rr = idx >> 3, sg = idx & 7;
            cp16(su32(smc + P2_V + bf * 256 * STRB + rr * STRB + sg * 16),
                 v_g + (size_t)rr * Ll + j0 + sg * 8);
        }
    };
    auto loadQ = [&](int bf, int j0) {
        if (tid < 32)
            cp16(su32(smc + P2_QS + bf * 512 + tid * 16), qs_g + j0 + tid * 2);
    };

    float C[2][8][4] = {};
    uint32_t frag[2][4][4];

    auto compP = [&](int kk, int j0n, const float4* qsb) {
        int jl = kk * 16 + 2 * c;
        float4 qA = qsb[jl >> 1];
        float4 qB = qsb[(jl >> 1) + 4];
        int gjA = j0n + jl, gjB = gjA + 8;
        #pragma unroll
        for (int u = 0; u < 4; ++u) {
            int gi = giV[u];
            float sti = stiV[u], ci = ciV[u];
            int dA0 = abs(gi - gjA), dA1 = abs(gi - gjA - 1);
            int dB0 = abs(gi - gjB), dB1 = abs(gi - gjB - 1);
            float xA0 = fmaf(fmaf(sti, qA.x, qA.y), sBase[dA0], ci);
            float xA1 = fmaf(fmaf(sti, qA.z, qA.w), sBase[dA1], ci);
            float xB0 = fmaf(fmaf(sti, qB.x, qB.y), sBase[dB0], ci);
            float xB1 = fmaf(fmaf(sti, qB.z, qB.w), sBase[dB1], ci);
            frag[u >> 1][kk][(u & 1)]     = packh2(ex2f(xA0), ex2f(xA1));
            frag[u >> 1][kk][(u & 1) + 2] = packh2(ex2f(xB0), ex2f(xB1));
        }
    };

    loadV(0, 0);
    loadQ(0, 0);
    loadQ(1, JT);
    CP_COMMIT();
    for (int t = tid; t < Ll; t += 512) sBase[t] = g_base[t];
    CP_WAIT0();
    __syncthreads();
    #pragma unroll
    for (int kk = 0; kk < 4; ++kk)
        compP(kk, 0, (const float4*)(smc + P2_QS));

    for (int t = 0; t < NC; ++t) {
        const int s = t & 1;
        if (t + 1 < NC) {
            loadV(s ^ 1, (t + 1) * JT);
            int j2 = (t + 2 < NC) ? (t + 2) * JT : 0;
            loadQ(t & 1, j2);
            CP_COMMIT();
        }
        const int jn0 = (t + 1 < NC) ? (t + 1) * JT : 0;
        const float4* qsb = (const float4*)(smc + P2_QS + ((t + 1) & 1) * 512);
        const uint32_t vS = su32(smc + P2_V + s * 256 * STRB);
        #pragma unroll
        for (int kk = 0; kk < 4; ++kk) {
            const uint32_t kb = kk * 32;
            #pragma unroll
            for (int nh = 0; nh < 2; ++nh) {
                uint32_t bh[2][4];
                #pragma unroll
                for (int q16 = 0; q16 < 2; ++q16) {
                    uint32_t off = (uint32_t)((wh * 64 + nh * 32 + q16 * 16) * STRB)
                                 + kb + lrB;
                    ldm4(bh[q16][0], bh[q16][1], bh[q16][2], bh[q16][3], vS + off);
                }
                #pragma unroll
                for (int mt = 0; mt < 2; ++mt) {
                    #pragma unroll
                    for (int q16 = 0; q16 < 2; ++q16) {
                        int nn = nh * 4 + q16 * 2;
                        mma16816h(C[mt][nn],     frag[mt][kk], bh[q16][0], bh[q16][1]);
                        mma16816h(C[mt][nn + 1], frag[mt][kk], bh[q16][2], bh[q16][3]);
                    }
                }
            }
            compP(kk, jn0, qsb);
        }
        if (t + 1 < NC) CP_WAIT0();
        __syncthreads();
    }

    // epilogue
    const int g = lane >> 2, tig = lane & 3;
    #pragma unroll
    for (int mt = 0; mt < 2; ++mt) {
        int row0 = i0 + wi * 32 + mt * 16 + g;
        float* o0 = out + ((size_t)b * Ll + row0) * Hh + wh * 64;
        float* o1 = out + ((size_t)b * Ll + row0 + 8) * Hh + wh * 64;
        #pragma unroll
        for (int nn = 0; nn < 8; ++nn) {
            int h = nn * 8 + tig * 2;
            *(float2*)(o0 + h) = make_float2(C[mt][nn][0], C[mt][nn][1]);
            *(float2*)(o1 + h) = make_float2(C[mt][nn][2], C[mt][nn][3]);
        }
    }
}

// ---------------- launch -----------------------------------------------------
extern "C" void kernel_launch(void* const* d_in, const int* in_sizes, int n_in,
                              void* d_out, int out_size) {
    const float* opinion = (const float*)d_in[0];
    const float* text    = (const float*)d_in[1];
    const int*   pos     = (const int*)d_in[2];
    const float* Wt      = (const float*)d_in[3];
    const float* bt      = (const float*)d_in[4];
    const float* Wo      = (const float*)d_in[5];
    const float* wa      = (const float*)d_in[6];
    const float* ba      = (const float*)d_in[7];
    float* out = (float*)d_out;

    prep_kernel<<<21056, 256>>>(pos, Wt, Wo, text, opinion);                 // 0
    cudaFuncSetAttribute((const void*)s1_mma_kernel,
                         cudaFuncAttributeMaxDynamicSharedMemorySize, S1_SMEM);
    s1_mma_kernel<<<256, 512, S1_SMEM>>>(bt, wa);                            // 1
    {
        dim3 g(Ll / 128, Bb);
        pass1_kernel<<<g, 256>>>(ba);                                        // 2
    }
    cudaFuncSetAttribute((const void*)pass2_kernel,
                         cudaFuncAttributeMaxDynamicSharedMemorySize, P2_SMEM);
    {
        dim3 g(Ll / 128, Bb);
        pass2_kernel<<<g, 512, P2_SMEM>>>(ba, out);                          // 3
    }
}

// round 12
// speedup vs baseline: 1.0395x; 1.0395x over previous
#include <cuda_runtime.h>
#include <cuda_bf16.h>
#include <cuda_fp16.h>
#include <math.h>
#include <cstdint>

constexpr int Bb = 8, Ll = 2048, Hh = 256;
constexpr int JT = 64, NC = Ll / JT;   // pass2 j-chunks
constexpr int STRB = 144;              // padded smem row stride (bytes), 9x16B

// ---------------- device scratch (allocation-free) ---------------------------
__device__ float  g_st[Bb * Ll];
__device__ float  g_so[Bb * Ll];
__device__ float  g_q [Bb * Ll];                     // mult_j * log2(e)
__device__ float2 g_qs[Bb * Ll];                     // {q_j, q_j * so_j}
__device__ float  g_c [Bb * Ll];                     // -(m̂_i + log2 l_i)
__device__ float  g_base[Ll];
__device__ __half g_vh[(size_t)Bb * Hh * Ll];        // V^T [B][H][L] fp16
__device__ __nv_bfloat16 g_whi[2 * Hh * Hh];         // W hi  [sel][h][k]
__device__ __nv_bfloat16 g_wlo[2 * Hh * Hh];         // W lo residual
__device__ __nv_bfloat16 g_xthi[Bb * Ll * Hh];       // text  hi [m][k]
__device__ __nv_bfloat16 g_xtlo[Bb * Ll * Hh];       // text  lo
__device__ __nv_bfloat16 g_xohi[Bb * Ll * Hh];       // opinion hi [m][k]
__device__ __nv_bfloat16 g_xolo[Bb * Ll * Hh];       // opinion lo

// ---------------- small helpers ----------------------------------------------
__device__ __forceinline__ uint32_t su32(const void* p) {
    return (uint32_t)__cvta_generic_to_shared(p);
}
__device__ __forceinline__ float ex2f(float x) {
    float r; asm("ex2.approx.f32 %0, %1;" : "=f"(r) : "f"(x)); return r;
}
__device__ __forceinline__ float lg2f(float x) {
    float r; asm("lg2.approx.f32 %0, %1;" : "=f"(r) : "f"(x)); return r;
}
__device__ __forceinline__ void ldm4(uint32_t& r0, uint32_t& r1, uint32_t& r2,
                                     uint32_t& r3, uint32_t a) {
    asm volatile("ldmatrix.sync.aligned.m8n8.x4.shared.b16 {%0,%1,%2,%3}, [%4];"
        : "=r"(r0), "=r"(r1), "=r"(r2), "=r"(r3) : "r"(a));
}
__device__ __forceinline__ void mma16816bf(float* c, const uint32_t* a,
                                           uint32_t b0, uint32_t b1) {
    asm volatile("mma.sync.aligned.m16n8k16.row.col.f32.bf16.bf16.f32 "
        "{%0,%1,%2,%3}, {%4,%5,%6,%7}, {%8,%9}, {%0,%1,%2,%3};"
        : "+f"(c[0]), "+f"(c[1]), "+f"(c[2]), "+f"(c[3])
        : "r"(a[0]), "r"(a[1]), "r"(a[2]), "r"(a[3]), "r"(b0), "r"(b1));
}
__device__ __forceinline__ void mma16816h(float* c, const uint32_t* a,
                                          uint32_t b0, uint32_t b1) {
    asm volatile("mma.sync.aligned.m16n8k16.row.col.f32.f16.f16.f32 "
        "{%0,%1,%2,%3}, {%4,%5,%6,%7}, {%8,%9}, {%0,%1,%2,%3};"
        : "+f"(c[0]), "+f"(c[1]), "+f"(c[2]), "+f"(c[3])
        : "r"(a[0]), "r"(a[1]), "r"(a[2]), "r"(a[3]), "r"(b0), "r"(b1));
}
__device__ __forceinline__ void split2(float p0, float p1, uint32_t& hi, uint32_t& lo) {
    asm("cvt.rn.bf16x2.f32 %0, %1, %2;" : "=r"(hi) : "f"(p1), "f"(p0));
    float h0 = __uint_as_float(hi << 16);
    float h1 = __uint_as_float(hi & 0xffff0000u);
    float r0 = p0 - h0, r1 = p1 - h1;
    asm("cvt.rn.bf16x2.f32 %0, %1, %2;" : "=r"(lo) : "f"(r1), "f"(r0));
}
__device__ __forceinline__ uint32_t packh2(float p0, float p1) {
    uint32_t r;
    asm("cvt.rn.f16x2.f32 %0, %1, %2;" : "=r"(r) : "f"(p1), "f"(p0));
    return r;
}
__device__ __forceinline__ void cp16(uint32_t dst, const void* src) {
    asm volatile("cp.async.cg.shared.global [%0], [%1], 16;"
        :: "r"(dst), "l"(src) : "memory");
}
#define CP_COMMIT() asm volatile("cp.async.commit_group;" ::: "memory")
#define CP_WAIT0()  asm volatile("cp.async.wait_group 0;" ::: "memory")

// ---------------- mega-prep: all preprocessing in one launch -----------------
__global__ __launch_bounds__(256) void prep_kernel(
    const int* __restrict__ pos, const float* __restrict__ Wt,
    const float* __restrict__ Wo, const float* __restrict__ Xt,
    const float* __restrict__ V)
{
    __shared__ float tile[32][33];
    const int blk = blockIdx.x, tid = threadIdx.x;
    if (blk < 64) {
        int idx = blk * 256 + tid;
        int p = pos[idx];
        bool op = (p >= 19 && p <= 21) || (p >= 33 && p <= 35) || (p >= 41 && p <= 46);
        g_q[idx] = (op ? 8.0f : 1.0f) * 1.44269504088896340736f;
        if (idx < Ll)
            g_base[idx] = (idx == 0) ? 0.5f : (1.0f / log2f(2.0f + (float)idx));
    } else if (blk < 576) {
        int idx = (blk - 64) * 256 + tid;
        int sel = idx >> 16, i = idx & (Hh * Hh - 1);
        float w = sel ? Wo[i] : Wt[i];
        __nv_bfloat16 hi = __float2bfloat16(w);
        g_whi[idx] = hi;
        g_wlo[idx] = __float2bfloat16(w - __bfloat162float(hi));
    } else if (blk < 16960) {
        int idx = (blk - 576) * 256 + tid;
        float v = Xt[idx];
        __nv_bfloat16 hi = __float2bfloat16(v);
        g_xthi[idx] = hi;
        g_xtlo[idx] = __float2bfloat16(v - __bfloat162float(hi));
    } else {
        int vz = blk - 16960;
        const int j0 = (vz & 63) * 32, h0 = ((vz >> 6) & 7) * 32, b = vz >> 9;
        const int c = tid & 31, r0 = tid >> 5;
        #pragma unroll
        for (int k = 0; k < 4; ++k) {
            int r = r0 + k * 8;
            size_t lin = ((size_t)b * Ll + j0 + r) * Hh + h0 + c;
            float v = V[lin];
            tile[r][c] = v;
            __nv_bfloat16 hi = __float2bfloat16(v);
            g_xohi[lin] = hi;
            g_xolo[lin] = __float2bfloat16(v - __bfloat162float(hi));
        }
        __syncthreads();
        #pragma unroll
        for (int k = 0; k < 4; ++k) {
            int hh = r0 + k * 8;
            g_vh[((size_t)b * Hh + h0 + hh) * Ll + j0 + c] = __float2half(tile[c][hh]);
        }
    }
}

// ---------------- stage 1: 256-thread bf16-split MMA + tanh·wa (R10) ---------
constexpr int S1_XHI = 0;                          // [2][128][STRB]
constexpr int S1_XLO = 2 * 128 * STRB;             // 36864
constexpr int S1_WHI = 4 * 128 * STRB;             // 73728  [2][256][STRB]
constexpr int S1_WLO = S1_WHI + 2 * 256 * STRB;    // 147456
constexpr int S1_RED = S1_WLO + 2 * 256 * STRB;    // 221184: float[4][128]
constexpr int S1_SMEM = S1_RED + 4 * 128 * 4;      // 223232

__global__ __launch_bounds__(256, 1) void s1_mma_kernel(
    const float* __restrict__ bt, const float* __restrict__ wa)
{
    extern __shared__ char smc[];
    const int tid = threadIdx.x, wid = tid >> 5, lane = tid & 31;
    const int sel = blockIdx.x >> 7;
    const int m0 = (blockIdx.x & 127) * 128;
    const int wi = wid >> 2, wh = wid & 3;

    const float* bias = sel ? nullptr : bt;
    const float* wah = wa + sel * Hh;
    const __nv_bfloat16* xhiG = (sel ? g_xohi : g_xthi) + (size_t)m0 * Hh;
    const __nv_bfloat16* xloG = (sel ? g_xolo : g_xtlo) + (size_t)m0 * Hh;
    const __nv_bfloat16* whiG = g_whi + sel * Hh * Hh;
    const __nv_bfloat16* wloG = g_wlo + sel * Hh * Hh;

    const int sub = lane >> 3, lr = lane & 7;
    const uint32_t lrA = (uint32_t)((lr + (sub & 1) * 8) * STRB + (sub >> 1) * 16);
    const uint32_t lrB = (uint32_t)((lr + (sub >> 1) * 8) * STRB + (sub & 1) * 16);

    float C[4][8][4] = {};

    auto fill = [&](int bf, int kc) {
        #pragma unroll
        for (int k = 0; k < 4; ++k) {
            int idx = tid + k * 256;
            int r = idx >> 3, seg = idx & 7;
            cp16(su32(smc + S1_XHI + bf * 128 * STRB + r * STRB + seg * 16),
                 xhiG + (size_t)r * Hh + kc * 64 + seg * 8);
            cp16(su32(smc + S1_XLO + bf * 128 * STRB + r * STRB + seg * 16),
                 xloG + (size_t)r * Hh + kc * 64 + seg * 8);
        }
        #pragma unroll
        for (int k = 0; k < 8; ++k) {
            int idx = tid + k * 256;
            int r = idx >> 3, seg = idx & 7;
            cp16(su32(smc + S1_WHI + bf * 256 * STRB + r * STRB + seg * 16),
                 whiG + (size_t)r * Hh + kc * 64 + seg * 8);
            cp16(su32(smc + S1_WLO + bf * 256 * STRB + r * STRB + seg * 16),
                 wloG + (size_t)r * Hh + kc * 64 + seg * 8);
        }
        CP_COMMIT();
    };

    fill(0, 0);
    CP_WAIT0();
    __syncthreads();

    for (int kc = 0; kc < 4; ++kc) {
        const int s = kc & 1;
        if (kc + 1 < 4) fill(s ^ 1, kc + 1);
        const uint32_t xhi = su32(smc + S1_XHI + s * 128 * STRB);
        const uint32_t xlo = su32(smc + S1_XLO + s * 128 * STRB);
        const uint32_t whi = su32(smc + S1_WHI + s * 256 * STRB);
        const uint32_t wlo = su32(smc + S1_WLO + s * 256 * STRB);
        #pragma unroll
        for (int kk = 0; kk < 4; ++kk) {
            const uint32_t kb = kk * 32;
            uint32_t bh[4][4], bl[4][4];
            #pragma unroll
            for (int nt = 0; nt < 4; ++nt) {
                uint32_t off = (uint32_t)((wh * 64 + nt * 16) * STRB) + kb + lrB;
                ldm4(bh[nt][0], bh[nt][1], bh[nt][2], bh[nt][3], whi + off);
                ldm4(bl[nt][0], bl[nt][1], bl[nt][2], bl[nt][3], wlo + off);
            }
            #pragma unroll
            for (int mt = 0; mt < 4; ++mt) {
                uint32_t aoff = (uint32_t)((wi * 64 + mt * 16) * STRB) + kb + lrA;
                uint32_t ah[4], al[4];
                ldm4(ah[0], ah[1], ah[2], ah[3], xhi + aoff);
                ldm4(al[0], al[1], al[2], al[3], xlo + aoff);
                #pragma unroll
                for (int nt = 0; nt < 4; ++nt) {
                    mma16816bf(C[mt][2 * nt],     ah, bh[nt][0], bh[nt][1]);
                    mma16816bf(C[mt][2 * nt + 1], ah, bh[nt][2], bh[nt][3]);
                }
                #pragma unroll
                for (int nt = 0; nt < 4; ++nt) {
                    mma16816bf(C[mt][2 * nt],     al, bh[nt][0], bh[nt][1]);
                    mma16816bf(C[mt][2 * nt + 1], al, bh[nt][2], bh[nt][3]);
                }
                #pragma unroll
                for (int nt = 0; nt < 4; ++nt) {
                    mma16816bf(C[mt][2 * nt],     ah, bl[nt][0], bl[nt][1]);
                    mma16816bf(C[mt][2 * nt + 1], ah, bl[nt][2], bl[nt][3]);
                }
            }
        }
        if (kc + 1 < 4) CP_WAIT0();
        __syncthreads();
    }

    float* sred = (float*)(smc + S1_RED);
    const int g = lane >> 2, tig = lane & 3;
    #pragma unroll
    for (int mt = 0; mt < 4; ++mt) {
        float p0 = 0.f, p1 = 0.f;
        #pragma unroll
        for (int nt = 0; nt < 8; ++nt) {
            int h = wh * 64 + nt * 8 + tig * 2;
            float b0 = bias ? __ldg(bias + h)     : 0.f;
            float b1 = bias ? __ldg(bias + h + 1) : 0.f;
            float w0 = __ldg(wah + h), w1 = __ldg(wah + h + 1);
            p0 += tanhf(C[mt][nt][0] + b0) * w0 + tanhf(C[mt][nt][1] + b1) * w1;
            p1 += tanhf(C[mt][nt][2] + b0) * w0 + tanhf(C[mt][nt][3] + b1) * w1;
        }
        p0 += __shfl_xor_sync(0xffffffffu, p0, 1);
        p0 += __shfl_xor_sync(0xffffffffu, p0, 2);
        p1 += __shfl_xor_sync(0xffffffffu, p1, 1);
        p1 += __shfl_xor_sync(0xffffffffu, p1, 2);
        if (tig == 0) {
            int row = wi * 64 + mt * 16 + g;
            sred[wh * 128 + row]     = p0;
            sred[wh * 128 + row + 8] = p1;
        }
    }
    __syncthreads();
    if (tid < 128) {
        float* outS = sel ? g_so : g_st;
        outS[m0 + tid] = sred[tid] + sred[128 + tid] + sred[256 + tid] + sred[384 + tid];
    }
}

// ---------------- pass 1: single-pass stats via safe max bound ---------------
__global__ __launch_bounds__(256) void pass1_kernel(const float* __restrict__ ba) {
    __shared__ float2 sQS[Ll];
    __shared__ float  sB[Ll];
    __shared__ float  sred[8];
    const int b = blockIdx.y, i0 = blockIdx.x * 128;
    const int tid = threadIdx.x, wid = tid >> 5, lane = tid & 31;

    float somax = -INFINITY;
    for (int t = tid; t < Ll; t += 256) {
        float so = g_so[b * Ll + t];
        float q  = g_q [b * Ll + t];
        float2 v = make_float2(q, q * so);
        sQS[t] = v;
        sB[t]  = g_base[t];
        if ((unsigned)(t - i0) < 128u) g_qs[b * Ll + t] = v;
        somax = fmaxf(somax, so);
    }
    #pragma unroll
    for (int off = 16; off > 0; off >>= 1)
        somax = fmaxf(somax, __shfl_xor_sync(0xffffffffu, somax, off));
    if (lane == 0) sred[wid] = somax;
    __syncthreads();
    somax = fmaxf(fmaxf(fmaxf(sred[0], sred[1]), fmaxf(sred[2], sred[3])),
                  fmaxf(fmaxf(sred[4], sred[5]), fmaxf(sred[6], sred[7])));

    const int row = tid >> 1, half = tid & 1;
    const int gi = i0 + row;
    const float A = g_st[b * Ll + gi] + ba[0];
    const float apm = A + somax;
    const float mhat = apm > 0.0f ? apm * 7.2825f : apm * 0.1311f;
    const int jb = half * 1024;

    float l = 0.f;
    #pragma unroll 4
    for (int t = 0; t < 1024; ++t) {
        int j = jb + t;
        int d = gi - j; d = d < 0 ? -d : d;
        float2 v = sQS[j];
        float x = fmaf(A, v.x, v.y) * sB[d];
        l += ex2f(x - mhat);
    }
    l += __shfl_xor_sync(0xffffffffu, l, 1);
    if (half == 0) g_c[b * Ll + gi] = -(mhat + lg2f(l));
}

// ---------------- pass 2: 2-block/SM register-P fp16 MMA attention -----------
// block = 64 i x 256 h, 256 threads, 8 warps as 4i x 2h (warp 16i x 128h).
// Mirrored base table: idx = j - gi + 2047 (no abs, immediate-offset LDS).
constexpr int P2_V    = 0;                        // [2][256*STRB] fp16 V^T
constexpr int P2_QS   = 2 * 256 * STRB;           // 73728, [2][512B]
constexpr int P2_BM   = P2_QS + 1024;             // 74752, float[4095]
constexpr int P2_SMEM = P2_BM + 4096 * 4;         // 91136  (x2 blocks = 182KB)

__global__ __launch_bounds__(256, 2) void pass2_kernel(
    const float* __restrict__ ba, float* __restrict__ out)
{
    extern __shared__ char smc[];
    const int tid = threadIdx.x, wid = tid >> 5, lane = tid & 31;
    const int b = blockIdx.y, i0 = blockIdx.x * 64;
    const int wi = wid >> 1;   // 0..3: 16-row tile
    const int wh = wid & 1;    // 0..1: 128 h-cols
    const int r = lane >> 2, c = lane & 3;

    float* sBaseM = (float*)(smc + P2_BM);

    const int sub = lane >> 3, lr = lane & 7;
    const uint32_t lrB = (uint32_t)((lr + (sub >> 1) * 8) * STRB + (sub & 1) * 16);

    const __half* v_g = g_vh + (size_t)b * Hh * Ll;
    const float2* qs_g = g_qs + b * Ll;

    const int gi0 = i0 + wi * 16 + r;
    const int gi1 = gi0 + 8;
    float sti0, sti1, ci0, ci1;
    {
        const float ba0 = __ldg(ba);
        sti0 = g_st[b * Ll + gi0] + ba0;
        sti1 = g_st[b * Ll + gi1] + ba0;
        ci0  = g_c [b * Ll + gi0];
        ci1  = g_c [b * Ll + gi1];
    }

    auto loadV = [&](int bf, int j0) {
        #pragma unroll
        for (int k = 0; k < 8; ++k) {
            int idx = tid + k * 256;
            int rr = idx >> 3, sg = idx & 7;
            cp16(su32(smc + P2_V + bf * 256 * STRB + rr * STRB + sg * 16),
                 v_g + (size_t)rr * Ll + j0 + sg * 8);
        }
    };
    auto loadQ = [&](int bf, int j0) {
        if (tid < 32)
            cp16(su32(smc + P2_QS + bf * 512 + tid * 16), qs_g + j0 + tid * 2);
    };

    float C[16][4] = {};
    uint32_t frag[4][4];

    auto compP = [&](int kk, int j0n, const float4* qsb) {
        int jl = kk * 16 + 2 * c;
        float4 qA = qsb[jl >> 1];
        float4 qB = qsb[(jl >> 1) + 4];
        int b0 = j0n + jl - gi0 + 2047;
        int b1 = j0n + jl - gi1 + 2047;
        float xA0 = fmaf(fmaf(sti0, qA.x, qA.y), sBaseM[b0],     ci0);
        float xA1 = fmaf(fmaf(sti0, qA.z, qA.w), sBaseM[b0 + 1], ci0);
        float xB0 = fmaf(fmaf(sti0, qB.x, qB.y), sBaseM[b0 + 8], ci0);
        float xB1 = fmaf(fmaf(sti0, qB.z, qB.w), sBaseM[b0 + 9], ci0);
        frag[kk][0] = packh2(ex2f(xA0), ex2f(xA1));
        frag[kk][2] = packh2(ex2f(xB0), ex2f(xB1));
        float yA0 = fmaf(fmaf(sti1, qA.x, qA.y), sBaseM[b1],     ci1);
        float yA1 = fmaf(fmaf(sti1, qA.z, qA.w), sBaseM[b1 + 1], ci1);
        float yB0 = fmaf(fmaf(sti1, qB.x, qB.y), sBaseM[b1 + 8], ci1);
        float yB1 = fmaf(fmaf(sti1, qB.z, qB.w), sBaseM[b1 + 9], ci1);
        frag[kk][1] = packh2(ex2f(yA0), ex2f(yA1));
        frag[kk][3] = packh2(ex2f(yB0), ex2f(yB1));
    };

    // prologue
    loadV(0, 0);
    loadQ(0, 0);
    loadQ(1, JT);
    CP_COMMIT();
    // mirrored base: sBaseM[t] = base(|t - 2047|), t in [0, 4095)
    for (int t = tid; t < 4095; t += 256) {
        int d = t - 2047; d = d < 0 ? -d : d;
        sBaseM[t] = g_base[d];
    }
    CP_WAIT0();
    __syncthreads();
    #pragma unroll
    for (int kk = 0; kk < 4; ++kk)
        compP(kk, 0, (const float4*)(smc + P2_QS));

    for (int t = 0; t < NC; ++t) {
        const int s = t & 1;
        if (t + 1 < NC) {
            loadV(s ^ 1, (t + 1) * JT);
            int j2 = (t + 2 < NC) ? (t + 2) * JT : 0;
            loadQ(t & 1, j2);
            CP_COMMIT();
        }
        const int jn0 = (t + 1 < NC) ? (t + 1) * JT : 0;
        const float4* qsb = (const float4*)(smc + P2_QS + ((t + 1) & 1) * 512);
        const uint32_t vS = su32(smc + P2_V + s * 256 * STRB);
        #pragma unroll
        for (int kk = 0; kk < 4; ++kk) {
            const uint32_t kb = kk * 32;
            #pragma unroll
            for (int nh = 0; nh < 2; ++nh) {
                uint32_t bh[4][4];
                #pragma unroll
                for (int q4 = 0; q4 < 4; ++q4) {
                    uint32_t off = (uint32_t)((wh * 128 + nh * 64 + q4 * 16) * STRB)
                                 + kb + lrB;
                    ldm4(bh[q4][0], bh[q4][1], bh[q4][2], bh[q4][3], vS + off);
                }
                #pragma unroll
                for (int q4 = 0; q4 < 4; ++q4) {
                    int nn = nh * 8 + q4 * 2;
                    mma16816h(C[nn],     frag[kk], bh[q4][0], bh[q4][1]);
                    mma16816h(C[nn + 1], frag[kk], bh[q4][2], bh[q4][3]);
                }
            }
            compP(kk, jn0, qsb);   // frag for chunk t+1, overlaps tensor drain
        }
        if (t + 1 < NC) CP_WAIT0();
        __syncthreads();
    }

    // epilogue: rows gi0 (lane r) and gi1 (+8), cols wh*128 + nn*8 + tig*2
    const int g = lane >> 2, tig = lane & 3;
    float* o0 = out + ((size_t)b * Ll + i0 + wi * 16 + g) * Hh + wh * 128;
    float* o1 = out + ((size_t)b * Ll + i0 + wi * 16 + g + 8) * Hh + wh * 128;
    #pragma unroll
    for (int nn = 0; nn < 16; ++nn) {
        int h = nn * 8 + tig * 2;
        *(float2*)(o0 + h) = make_float2(C[nn][0], C[nn][1]);
        *(float2*)(o1 + h) = make_float2(C[nn][2], C[nn][3]);
    }
}

// ---------------- launch -----------------------------------------------------
extern "C" void kernel_launch(void* const* d_in, const int* in_sizes, int n_in,
                              void* d_out, int out_size) {
    const float* opinion = (const float*)d_in[0];
    const float* text    = (const float*)d_in[1];
    const int*   pos     = (const int*)d_in[2];
    const float* Wt      = (const float*)d_in[3];
    const float* bt      = (const float*)d_in[4];
    const float* Wo      = (const float*)d_in[5];
    const float* wa      = (const float*)d_in[6];
    const float* ba      = (const float*)d_in[7];
    float* out = (float*)d_out;

    prep_kernel<<<21056, 256>>>(pos, Wt, Wo, text, opinion);                 // 0
    cudaFuncSetAttribute((const void*)s1_mma_kernel,
                         cudaFuncAttributeMaxDynamicSharedMemorySize, S1_SMEM);
    s1_mma_kernel<<<256, 256, S1_SMEM>>>(bt, wa);                            // 1
    {
        dim3 g(Ll / 128, Bb);
        pass1_kernel<<<g, 256>>>(ba);                                        // 2
    }
    cudaFuncSetAttribute((const void*)pass2_kernel,
                         cudaFuncAttributeMaxDynamicSharedMemorySize, P2_SMEM);
    {
        dim3 g(Ll / 64, Bb);
        pass2_kernel<<<g, 256, P2_SMEM>>>(ba, out);                          // 3
    }
}

// round 13
// speedup vs baseline: 1.1727x; 1.1282x over previous
#include <cuda_runtime.h>
#include <cuda_bf16.h>
#include <cuda_fp16.h>
#include <math.h>
#include <cstdint>

constexpr int Bb = 8, Ll = 2048, Hh = 256;
constexpr int JT = 64, NC = Ll / JT;   // pass2 j-chunks
constexpr int STRB = 144;              // padded smem row stride (bytes), 9x16B

// ---------------- device scratch (allocation-free) ---------------------------
__device__ float  g_sp[2][2][Bb * Ll];               // [sel][h-half] partial sums
__device__ float  g_st[Bb * Ll];                     // combined st (pass1 writes)
__device__ float  g_q [Bb * Ll];                     // mult_j * log2(e)
__device__ float2 g_qs[Bb * Ll];                     // {q_j, q_j * so_j}
__device__ float  g_c [Bb * Ll];                     // -(m̂_i + log2 l_i)
__device__ float  g_base[Ll];
__device__ __half g_vh[(size_t)Bb * Hh * Ll];        // V^T [B][H][L] fp16
__device__ __nv_bfloat16 g_whi[2 * Hh * Hh];         // W hi  [sel][h][k]
__device__ __nv_bfloat16 g_wlo[2 * Hh * Hh];         // W lo residual
__device__ __nv_bfloat16 g_xthi[Bb * Ll * Hh];       // text  hi [m][k]
__device__ __nv_bfloat16 g_xtlo[Bb * Ll * Hh];       // text  lo
__device__ __nv_bfloat16 g_xohi[Bb * Ll * Hh];       // opinion hi [m][k]
__device__ __nv_bfloat16 g_xolo[Bb * Ll * Hh];       // opinion lo

// ---------------- small helpers ----------------------------------------------
__device__ __forceinline__ uint32_t su32(const void* p) {
    return (uint32_t)__cvta_generic_to_shared(p);
}
__device__ __forceinline__ float ex2f(float x) {
    float r; asm("ex2.approx.f32 %0, %1;" : "=f"(r) : "f"(x)); return r;
}
__device__ __forceinline__ float lg2f(float x) {
    float r; asm("lg2.approx.f32 %0, %1;" : "=f"(r) : "f"(x)); return r;
}
__device__ __forceinline__ void ldm4(uint32_t& r0, uint32_t& r1, uint32_t& r2,
                                     uint32_t& r3, uint32_t a) {
    asm volatile("ldmatrix.sync.aligned.m8n8.x4.shared.b16 {%0,%1,%2,%3}, [%4];"
        : "=r"(r0), "=r"(r1), "=r"(r2), "=r"(r3) : "r"(a));
}
__device__ __forceinline__ void mma16816bf(float* c, const uint32_t* a,
                                           uint32_t b0, uint32_t b1) {
    asm volatile("mma.sync.aligned.m16n8k16.row.col.f32.bf16.bf16.f32 "
        "{%0,%1,%2,%3}, {%4,%5,%6,%7}, {%8,%9}, {%0,%1,%2,%3};"
        : "+f"(c[0]), "+f"(c[1]), "+f"(c[2]), "+f"(c[3])
        : "r"(a[0]), "r"(a[1]), "r"(a[2]), "r"(a[3]), "r"(b0), "r"(b1));
}
__device__ __forceinline__ void mma16816h(float* c, const uint32_t* a,
                                          uint32_t b0, uint32_t b1) {
    asm volatile("mma.sync.aligned.m16n8k16.row.col.f32.f16.f16.f32 "
        "{%0,%1,%2,%3}, {%4,%5,%6,%7}, {%8,%9}, {%0,%1,%2,%3};"
        : "+f"(c[0]), "+f"(c[1]), "+f"(c[2]), "+f"(c[3])
        : "r"(a[0]), "r"(a[1]), "r"(a[2]), "r"(a[3]), "r"(b0), "r"(b1));
}
__device__ __forceinline__ void split2(float p0, float p1, uint32_t& hi, uint32_t& lo) {
    asm("cvt.rn.bf16x2.f32 %0, %1, %2;" : "=r"(hi) : "f"(p1), "f"(p0));
    float h0 = __uint_as_float(hi << 16);
    float h1 = __uint_as_float(hi & 0xffff0000u);
    float r0 = p0 - h0, r1 = p1 - h1;
    asm("cvt.rn.bf16x2.f32 %0, %1, %2;" : "=r"(lo) : "f"(r1), "f"(r0));
}
__device__ __forceinline__ uint32_t packh2(float p0, float p1) {
    uint32_t r;
    asm("cvt.rn.f16x2.f32 %0, %1, %2;" : "=r"(r) : "f"(p1), "f"(p0));
    return r;
}
__device__ __forceinline__ void cp16(uint32_t dst, const void* src) {
    asm volatile("cp.async.cg.shared.global [%0], [%1], 16;"
        :: "r"(dst), "l"(src) : "memory");
}
#define CP_COMMIT() asm volatile("cp.async.commit_group;" ::: "memory")
#define CP_WAIT0()  asm volatile("cp.async.wait_group 0;" ::: "memory")

// ---------------- mega-prep: all preprocessing in one launch -----------------
// zones: [0,64) pos/base | [64,576) W split | [576,4672) text split x4 |
//        [4672,8768) V^T + opinion split
__global__ __launch_bounds__(256) void prep_kernel(
    const int* __restrict__ pos, const float* __restrict__ Wt,
    const float* __restrict__ Wo, const float* __restrict__ Xt,
    const float* __restrict__ V)
{
    __shared__ float tile[32][33];
    const int blk = blockIdx.x, tid = threadIdx.x;
    if (blk < 64) {
        int idx = blk * 256 + tid;
        int p = pos[idx];
        bool op = (p >= 19 && p <= 21) || (p >= 33 && p <= 35) || (p >= 41 && p <= 46);
        g_q[idx] = (op ? 8.0f : 1.0f) * 1.44269504088896340736f;
        if (idx < Ll)
            g_base[idx] = (idx == 0) ? 0.5f : (1.0f / log2f(2.0f + (float)idx));
    } else if (blk < 576) {
        int idx = (blk - 64) * 256 + tid;
        int sel = idx >> 16, i = idx & (Hh * Hh - 1);
        float w = sel ? Wo[i] : Wt[i];
        __nv_bfloat16 hi = __float2bfloat16(w);
        g_whi[idx] = hi;
        g_wlo[idx] = __float2bfloat16(w - __bfloat162float(hi));
    } else if (blk < 4672) {
        int i4 = (blk - 576) * 256 + tid;
        float4 v = ((const float4*)Xt)[i4];
        uint32_t h01, l01, h23, l23;
        split2(v.x, v.y, h01, l01);
        split2(v.z, v.w, h23, l23);
        ((uint2*)g_xthi)[i4] = make_uint2(h01, h23);
        ((uint2*)g_xtlo)[i4] = make_uint2(l01, l23);
    } else {
        int vz = blk - 4672;
        const int j0 = (vz & 63) * 32, h0 = ((vz >> 6) & 7) * 32, b = vz >> 9;
        const int c = tid & 31, r0 = tid >> 5;
        #pragma unroll
        for (int k = 0; k < 4; ++k) {
            int r = r0 + k * 8;
            size_t lin = ((size_t)b * Ll + j0 + r) * Hh + h0 + c;
            float v = V[lin];
            tile[r][c] = v;
            __nv_bfloat16 hi = __float2bfloat16(v);
            g_xohi[lin] = hi;
            g_xolo[lin] = __float2bfloat16(v - __bfloat162float(hi));
        }
        __syncthreads();
        #pragma unroll
        for (int k = 0; k < 4; ++k) {
            int hh = r0 + k * 8;
            g_vh[((size_t)b * Hh + h0 + hh) * Ll + j0 + c] = __float2half(tile[c][hh]);
        }
    }
}

// ---------------- stage 1: h-split 2-block/SM bf16 MMA + tanh·wa -------------
// grid 512: bx = mb*4 + hh*2 + sel. Block = 128m x 128h, single-buffered.
// 8 warps as 2m x 4h (warp 64m x 32h, C=64 regs).
constexpr int S1_XHI = 0;                          // [128][STRB]
constexpr int S1_XLO = 128 * STRB;                 // 18432
constexpr int S1_WHI = 2 * 128 * STRB;             // 36864
constexpr int S1_WLO = 3 * 128 * STRB;             // 55296
constexpr int S1_RED = 4 * 128 * STRB;             // 73728: float[4][128]
constexpr int S1_SMEM = S1_RED + 4 * 128 * 4;      // 75776  (x2 = 151.5KB/SM)

__global__ __launch_bounds__(256, 2) void s1_mma_kernel(
    const float* __restrict__ bt, const float* __restrict__ wa)
{
    extern __shared__ char smc[];
    const int tid = threadIdx.x, wid = tid >> 5, lane = tid & 31;
    const int sel = blockIdx.x & 1;
    const int hh  = (blockIdx.x >> 1) & 1;
    const int m0  = (blockIdx.x >> 2) * 128;
    const int h0  = hh * 128;
    const int wi = wid >> 2;     // 0..1: 64 m-rows
    const int wh = wid & 3;      // 0..3: 32 h-cols

    const float* bias = sel ? nullptr : bt;
    const float* wah = wa + sel * Hh;
    const __nv_bfloat16* xhiG = (sel ? g_xohi : g_xthi) + (size_t)m0 * Hh;
    const __nv_bfloat16* xloG = (sel ? g_xolo : g_xtlo) + (size_t)m0 * Hh;
    const __nv_bfloat16* whiG = g_whi + sel * Hh * Hh + (size_t)h0 * Hh;
    const __nv_bfloat16* wloG = g_wlo + sel * Hh * Hh + (size_t)h0 * Hh;

    const int sub = lane >> 3, lr = lane & 7;
    const uint32_t lrA = (uint32_t)((lr + (sub & 1) * 8) * STRB + (sub >> 1) * 16);
    const uint32_t lrB = (uint32_t)((lr + (sub >> 1) * 8) * STRB + (sub & 1) * 16);

    float C[4][4][4] = {};

    for (int kc = 0; kc < 4; ++kc) {
        // fill (single buffer): X 128x64, W 128x64, hi+lo, all cp.async
        #pragma unroll
        for (int k = 0; k < 4; ++k) {
            int idx = tid + k * 256;
            int r = idx >> 3, seg = idx & 7;
            cp16(su32(smc + S1_XHI + r * STRB + seg * 16),
                 xhiG + (size_t)r * Hh + kc * 64 + seg * 8);
            cp16(su32(smc + S1_XLO + r * STRB + seg * 16),
                 xloG + (size_t)r * Hh + kc * 64 + seg * 8);
            cp16(su32(smc + S1_WHI + r * STRB + seg * 16),
                 whiG + (size_t)r * Hh + kc * 64 + seg * 8);
            cp16(su32(smc + S1_WLO + r * STRB + seg * 16),
                 wloG + (size_t)r * Hh + kc * 64 + seg * 8);
        }
        CP_COMMIT();
        CP_WAIT0();
        __syncthreads();

        const uint32_t xhi = su32(smc + S1_XHI);
        const uint32_t xlo = su32(smc + S1_XLO);
        const uint32_t whi = su32(smc + S1_WHI);
        const uint32_t wlo = su32(smc + S1_WLO);
        #pragma unroll
        for (int kk = 0; kk < 4; ++kk) {
            const uint32_t kb = kk * 32;
            uint32_t bh[2][4], bl[2][4];
            #pragma unroll
            for (int nt2 = 0; nt2 < 2; ++nt2) {
                uint32_t off = (uint32_t)((wh * 32 + nt2 * 16) * STRB) + kb + lrB;
                ldm4(bh[nt2][0], bh[nt2][1], bh[nt2][2], bh[nt2][3], whi + off);
                ldm4(bl[nt2][0], bl[nt2][1], bl[nt2][2], bl[nt2][3], wlo + off);
            }
            #pragma unroll
            for (int mt = 0; mt < 4; ++mt) {
                uint32_t aoff = (uint32_t)((wi * 64 + mt * 16) * STRB) + kb + lrA;
                uint32_t ah[4], al[4];
                ldm4(ah[0], ah[1], ah[2], ah[3], xhi + aoff);
                ldm4(al[0], al[1], al[2], al[3], xlo + aoff);
                #pragma unroll
                for (int nt2 = 0; nt2 < 2; ++nt2) {
                    mma16816bf(C[mt][2 * nt2],     ah, bh[nt2][0], bh[nt2][1]);
                    mma16816bf(C[mt][2 * nt2 + 1], ah, bh[nt2][2], bh[nt2][3]);
                }
                #pragma unroll
                for (int nt2 = 0; nt2 < 2; ++nt2) {
                    mma16816bf(C[mt][2 * nt2],     al, bh[nt2][0], bh[nt2][1]);
                    mma16816bf(C[mt][2 * nt2 + 1], al, bh[nt2][2], bh[nt2][3]);
                }
                #pragma unroll
                for (int nt2 = 0; nt2 < 2; ++nt2) {
                    mma16816bf(C[mt][2 * nt2],     ah, bl[nt2][0], bl[nt2][1]);
                    mma16816bf(C[mt][2 * nt2 + 1], ah, bl[nt2][2], bl[nt2][3]);
                }
            }
        }
        __syncthreads();   // tiles consumed before next fill overwrites
    }

    // epilogue: partial s over this block's 128 h -> g_sp[sel][hh]
    float* sred = (float*)(smc + S1_RED);
    const int g = lane >> 2, tig = lane & 3;
    #pragma unroll
    for (int mt = 0; mt < 4; ++mt) {
        float p0 = 0.f, p1 = 0.f;
        #pragma unroll
        for (int nt = 0; nt < 4; ++nt) {
            int h = h0 + wh * 32 + nt * 8 + tig * 2;
            float b0 = bias ? __ldg(bias + h)     : 0.f;
            float b1 = bias ? __ldg(bias + h + 1) : 0.f;
            float w0 = __ldg(wah + h), w1 = __ldg(wah + h + 1);
            p0 += tanhf(C[mt][nt][0] + b0) * w0 + tanhf(C[mt][nt][1] + b1) * w1;
            p1 += tanhf(C[mt][nt][2] + b0) * w0 + tanhf(C[mt][nt][3] + b1) * w1;
        }
        p0 += __shfl_xor_sync(0xffffffffu, p0, 1);
        p0 += __shfl_xor_sync(0xffffffffu, p0, 2);
        p1 += __shfl_xor_sync(0xffffffffu, p1, 1);
        p1 += __shfl_xor_sync(0xffffffffu, p1, 2);
        if (tig == 0) {
            int row = wi * 64 + mt * 16 + g;
            sred[wh * 128 + row]     = p0;
            sred[wh * 128 + row + 8] = p1;
        }
    }
    __syncthreads();
    if (tid < 128)
        g_sp[sel][hh][m0 + tid] =
            sred[tid] + sred[128 + tid] + sred[256 + tid] + sred[384 + tid];
}

// ---------------- pass 1: combine partials + single-pass stats ---------------
__global__ __launch_bounds__(256) void pass1_kernel(const float* __restrict__ ba) {
    __shared__ float2 sQS[Ll];
    __shared__ float  sB[Ll];
    __shared__ float  sred[8];
    const int b = blockIdx.y, i0 = blockIdx.x * 128;
    const int tid = threadIdx.x, wid = tid >> 5, lane = tid & 31;

    float somax = -INFINITY;
    for (int t = tid; t < Ll; t += 256) {
        float so = g_sp[1][0][b * Ll + t] + g_sp[1][1][b * Ll + t];
        float q  = g_q[b * Ll + t];
        float2 v = make_float2(q, q * so);
        sQS[t] = v;
        sB[t]  = g_base[t];
        if ((unsigned)(t - i0) < 128u) g_qs[b * Ll + t] = v;
        somax = fmaxf(somax, so);
    }
    #pragma unroll
    for (int off = 16; off > 0; off >>= 1)
        somax = fmaxf(somax, __shfl_xor_sync(0xffffffffu, somax, off));
    if (lane == 0) sred[wid] = somax;
    __syncthreads();
    somax = fmaxf(fmaxf(fmaxf(sred[0], sred[1]), fmaxf(sred[2], sred[3])),
                  fmaxf(fmaxf(sred[4], sred[5]), fmaxf(sred[6], sred[7])));

    const int row = tid >> 1, half = tid & 1;
    const int gi = i0 + row;
    const float stsum = g_sp[0][0][b * Ll + gi] + g_sp[0][1][b * Ll + gi];
    if (half == 0) g_st[b * Ll + gi] = stsum;      // combined st for pass2
    const float A = stsum + ba[0];
    const float apm = A + somax;
    const float mhat = apm > 0.0f ? apm * 7.2825f : apm * 0.1311f;
    const int jb = half * 1024;

    float l = 0.f;
    #pragma unroll 4
    for (int t = 0; t < 1024; ++t) {
        int j = jb + t;
        int d = gi - j; d = d < 0 ? -d : d;
        float2 v = sQS[j];
        float x = fmaf(A, v.x, v.y) * sB[d];
        l += ex2f(x - mhat);
    }
    l += __shfl_xor_sync(0xffffffffu, l, 1);
    if (half == 0) g_c[b * Ll + gi] = -(mhat + lg2f(l));
}

// ---------------- pass 2: 2-block/SM register-P fp16 MMA (R12) ---------------
constexpr int P2_V    = 0;                        // [2][256*STRB] fp16 V^T
constexpr int P2_QS   = 2 * 256 * STRB;           // 73728, [2][512B]
constexpr int P2_BM   = P2_QS + 1024;             // 74752, float[4095]
constexpr int P2_SMEM = P2_BM + 4096 * 4;         // 91136  (x2 = 182KB)

__global__ __launch_bounds__(256, 2) void pass2_kernel(
    const float* __restrict__ ba, float* __restrict__ out)
{
    extern __shared__ char smc[];
    const int tid = threadIdx.x, wid = tid >> 5, lane = tid & 31;
    const int b = blockIdx.y, i0 = blockIdx.x * 64;
    const int wi = wid >> 1;   // 0..3: 16-row tile
    const int wh = wid & 1;    // 0..1: 128 h-cols
    const int r = lane >> 2, c = lane & 3;

    float* sBaseM = (float*)(smc + P2_BM);

    const int sub = lane >> 3, lr = lane & 7;
    const uint32_t lrB = (uint32_t)((lr + (sub >> 1) * 8) * STRB + (sub & 1) * 16);

    const __half* v_g = g_vh + (size_t)b * Hh * Ll;
    const float2* qs_g = g_qs + b * Ll;

    const int gi0 = i0 + wi * 16 + r;
    const int gi1 = gi0 + 8;
    float sti0, sti1, ci0, ci1;
    {
        const float ba0 = __ldg(ba);
        sti0 = g_st[b * Ll + gi0] + ba0;
        sti1 = g_st[b * Ll + gi1] + ba0;
        ci0  = g_c [b * Ll + gi0];
        ci1  = g_c [b * Ll + gi1];
    }

    auto loadV = [&](int bf, int j0) {
        #pragma unroll
        for (int k = 0; k < 8; ++k) {
            int idx = tid + k * 256;
            int rr = idx >> 3, sg = idx & 7;
            cp16(su32(smc + P2_V + bf * 256 * STRB + rr * STRB + sg * 16),
                 v_g + (size_t)rr * Ll + j0 + sg * 8);
        }
    };
    auto loadQ = [&](int bf, int j0) {
        if (tid < 32)
            cp16(su32(smc + P2_QS + bf * 512 + tid * 16), qs_g + j0 + tid * 2);
    };

    float C[16][4] = {};
    uint32_t frag[4][4];

    auto compP = [&](int kk, int j0n, const float4* qsb) {
        int jl = kk * 16 + 2 * c;
        float4 qA = qsb[jl >> 1];
        float4 qB = qsb[(jl >> 1) + 4];
        int b0 = j0n + jl - gi0 + 2047;
        int b1 = j0n + jl - gi1 + 2047;
        float xA0 = fmaf(fmaf(sti0, qA.x, qA.y), sBaseM[b0],     ci0);
        float xA1 = fmaf(fmaf(sti0, qA.z, qA.w), sBaseM[b0 + 1], ci0);
        float xB0 = fmaf(fmaf(sti0, qB.x, qB.y), sBaseM[b0 + 8], ci0);
        float xB1 = fmaf(fmaf(sti0, qB.z, qB.w), sBaseM[b0 + 9], ci0);
        frag[kk][0] = packh2(ex2f(xA0), ex2f(xA1));
        frag[kk][2] = packh2(ex2f(xB0), ex2f(xB1));
        float yA0 = fmaf(fmaf(sti1, qA.x, qA.y), sBaseM[b1],     ci1);
        float yA1 = fmaf(fmaf(sti1, qA.z, qA.w), sBaseM[b1 + 1], ci1);
        float yB0 = fmaf(fmaf(sti1, qB.x, qB.y), sBaseM[b1 + 8], ci1);
        float yB1 = fmaf(fmaf(sti1, qB.z, qB.w), sBaseM[b1 + 9], ci1);
        frag[kk][1] = packh2(ex2f(yA0), ex2f(yA1));
        frag[kk][3] = packh2(ex2f(yB0), ex2f(yB1));
    };

    loadV(0, 0);
    loadQ(0, 0);
    loadQ(1, JT);
    CP_COMMIT();
    for (int t = tid; t < 4095; t += 256) {
        int d = t - 2047; d = d < 0 ? -d : d;
        sBaseM[t] = g_base[d];
    }
    CP_WAIT0();
    __syncthreads();
    #pragma unroll
    for (int kk = 0; kk < 4; ++kk)
        compP(kk, 0, (const float4*)(smc + P2_QS));

    for (int t = 0; t < NC; ++t) {
        const int s = t & 1;
        if (t + 1 < NC) {
            loadV(s ^ 1, (t + 1) * JT);
            int j2 = (t + 2 < NC) ? (t + 2) * JT : 0;
            loadQ(t & 1, j2);
            CP_COMMIT();
        }
        const int jn0 = (t + 1 < NC) ? (t + 1) * JT : 0;
        const float4* qsb = (const float4*)(smc + P2_QS + ((t + 1) & 1) * 512);
        const uint32_t vS = su32(smc + P2_V + s * 256 * STRB);
        #pragma unroll
        for (int kk = 0; kk < 4; ++kk) {
            const uint32_t kb = kk * 32;
            #pragma unroll
            for (int nh = 0; nh < 2; ++nh) {
                uint32_t bh[4][4];
                #pragma unroll
                for (int q4 = 0; q4 < 4; ++q4) {
                    uint32_t off = (uint32_t)((wh * 128 + nh * 64 + q4 * 16) * STRB)
                                 + kb + lrB;
                    ldm4(bh[q4][0], bh[q4][1], bh[q4][2], bh[q4][3], vS + off);
                }
                #pragma unroll
                for (int q4 = 0; q4 < 4; ++q4) {
                    int nn = nh * 8 + q4 * 2;
                    mma16816h(C[nn],     frag[kk], bh[q4][0], bh[q4][1]);
                    mma16816h(C[nn + 1], frag[kk], bh[q4][2], bh[q4][3]);
                }
            }
            compP(kk, jn0, qsb);
        }
        if (t + 1 < NC) CP_WAIT0();
        __syncthreads();
    }

    const int g = lane >> 2, tig = lane & 3;
    float* o0 = out + ((size_t)b * Ll + i0 + wi * 16 + g) * Hh + wh * 128;
    float* o1 = out + ((size_t)b * Ll + i0 + wi * 16 + g + 8) * Hh + wh * 128;
    #pragma unroll
    for (int nn = 0; nn < 16; ++nn) {
        int h = nn * 8 + tig * 2;
        *(float2*)(o0 + h) = make_float2(C[nn][0], C[nn][1]);
        *(float2*)(o1 + h) = make_float2(C[nn][2], C[nn][3]);
    }
}

// ---------------- launch -----------------------------------------------------
extern "C" void kernel_launch(void* const* d_in, const int* in_sizes, int n_in,
                              void* d_out, int out_size) {
    const float* opinion = (const float*)d_in[0];
    const float* text    = (const float*)d_in[1];
    const int*   pos     = (const int*)d_in[2];
    const float* Wt      = (const float*)d_in[3];
    const float* bt      = (const float*)d_in[4];
    const float* Wo      = (const float*)d_in[5];
    const float* wa      = (const float*)d_in[6];
    const float* ba      = (const float*)d_in[7];
    float* out = (float*)d_out;

    prep_kernel<<<8768, 256>>>(pos, Wt, Wo, text, opinion);                  // 0
    cudaFuncSetAttribute((const void*)s1_mma_kernel,
                         cudaFuncAttributeMaxDynamicSharedMemorySize, S1_SMEM);
    s1_mma_kernel<<<512, 256, S1_SMEM>>>(bt, wa);                            // 1
    {
        dim3 g(Ll / 128, Bb);
        pass1_kernel<<<g, 256>>>(ba);                                        // 2
    }
    cudaFuncSetAttribute((const void*)pass2_kernel,
                         cudaFuncAttributeMaxDynamicSharedMemorySize, P2_SMEM);
    {
        dim3 g(Ll / 64, Bb);
        pass2_kernel<<<g, 256, P2_SMEM>>>(ba, out);                          // 3
    }
}